// round 4
// baseline (speedup 1.0000x reference)
#include <cuda_runtime.h>

// ---------------------------------------------------------------------------
// DFMNET: 2-layer LSTM (B=2048, T=256, I=64, H=128) + 6-layer MLP head.
// Persistent CTA per 16 batch rows runs all 256 timesteps.
// R4: 512 threads/CTA (4 warps/SMSP for latency hiding), rows-split thread
// mapping (2 gate cols x 8 rows/thread), pre-duplicated f32x2 weights
// (LDG.64, no pack MOVs), xh[k][16] broadcast-friendly smem layout.
// fp32 FFMA2 floor = 28.7K cyc/step/SM; target ~80% of it.
// ---------------------------------------------------------------------------

#define T_SEQ    256
#define I_IN     64
#define H_HID    128
#define ROWS     16            // batch rows per CTA
#define NTHREADS 512
#define KROWS    320           // xh rows: [x(64) | h1(128) | h2(128)]
#define GSTR     516           // gates row stride (padded: 516 % 32 == 4 -> 2-way reads)

typedef unsigned long long ull;

// Repacked weights: k-major [k][512], each element duplicated into both
// halves of a 64-bit word so FFMA2 consumes it directly (no pack MOV).
__device__ ull   g_Wt1[192 * 512];
__device__ ull   g_Wt2[256 * 512];
__device__ ull   g_b1[512];         // (b_ih + b_hh) duplicated
__device__ ull   g_b2[512];

// ---- packed fp32x2 helpers ----
__device__ __forceinline__ ull fma2(ull a, ull b, ull c) {
    ull d;
    asm("fma.rn.f32x2 %0, %1, %2, %3;" : "=l"(d) : "l"(a), "l"(b), "l"(c));
    return d;
}
__device__ __forceinline__ void unpack2(ull v, float& lo, float& hi) {
    unsigned a, b;
    asm("mov.b64 {%0, %1}, %2;" : "=r"(a), "=r"(b) : "l"(v));
    lo = __uint_as_float(a); hi = __uint_as_float(b);
}
__device__ __forceinline__ ull dup_host(float w) {   // used device-side in prep
    ull r; unsigned u = __float_as_uint(w);
    asm("mov.b64 %0, {%1, %1};" : "=l"(r) : "r"(u));
    return r;
}

__device__ __forceinline__ float sigf(float v) {
    return __fdividef(1.f, 1.f + __expf(-v));
}
__device__ __forceinline__ float tanhf_fast(float v) {
    float z = fminf(fmaxf(v, -15.f), 15.f);
    float e = __expf(-2.f * z);
    return __fdividef(1.f - e, 1.f + e);
}

// ---------------------------------------------------------------------------
// Weight repack: fuse (W_ih | W_hh), transpose to k-major, duplicate to f32x2.
// ---------------------------------------------------------------------------
__global__ void prep_kernel(const float* __restrict__ Wih1, const float* __restrict__ Whh1,
                            const float* __restrict__ bih1, const float* __restrict__ bhh1,
                            const float* __restrict__ Wih2, const float* __restrict__ Whh2,
                            const float* __restrict__ bih2, const float* __restrict__ bhh2)
{
    int tid = blockIdx.x * blockDim.x + threadIdx.x;
    int stride = gridDim.x * blockDim.x;
    if (tid < 512) {
        g_b1[tid] = dup_host(bih1[tid] + bhh1[tid]);
        g_b2[tid] = dup_host(bih2[tid] + bhh2[tid]);
    }
    for (int e = tid; e < 192 * 512; e += stride) {
        int k = e >> 9, g = e & 511;
        float w = (k < 64) ? Wih1[g * 64 + k] : Whh1[g * 128 + (k - 64)];
        g_Wt1[e] = dup_host(w);
    }
    for (int e = tid; e < 256 * 512; e += stride) {
        int k = e >> 9, g = e & 511;
        float w = (k < 128) ? Wih2[g * 128 + k] : Whh2[g * 128 + (k - 128)];
        g_Wt2[e] = dup_host(w);
    }
}

// ---------------------------------------------------------------------------
// Gate GEMM: gates[16][GSTR] = bias + xh[16][K] @ Wt[K][512]
// 512 threads: half = tid>>8 selects rows [8*half, 8*half+8); thread owns gate
// columns g0 = tid&255 and g1 = g0+256 for its 8 rows (4 f32x2 accs per col).
// Weights double-buffered in 4-k chunks (256-cyc wall per chunk covers L2 lat).
// q loads are warp-uniform broadcasts (conflict-free).
// ---------------------------------------------------------------------------
__device__ __forceinline__ void gemm_gates(const ull* __restrict__ Wt,
                                           const ull* __restrict__ bias,
                                           const float* __restrict__ xh,   // [k][16]
                                           float* __restrict__ gates,      // [16][GSTR]
                                           int K, int tid)
{
    const int half = tid >> 8;            // 0/1: which 8-row group
    const int g0 = tid & 255;
    const int g1 = g0 + 256;
    const float* xhp = xh + half * 8;     // row offset within each k-row

    ull acc0[4], acc1[4];
    {
        ull b0 = bias[g0], b1 = bias[g1];
#pragma unroll
        for (int p = 0; p < 4; p++) { acc0[p] = b0; acc1[p] = b1; }
    }

    const ull* W0 = Wt + g0;
    const ull* W1 = Wt + g1;

    ull wc0[4], wc1[4];
#pragma unroll
    for (int j = 0; j < 4; j++) { wc0[j] = W0[j * 512]; wc1[j] = W1[j * 512]; }

    for (int k0 = 0; k0 < K; k0 += 4) {
        // prefetch next weight chunk (wraps to 0 on last chunk; values unused)
        int kp = (k0 + 4 < K) ? (k0 + 4) : 0;
        ull wn0[4], wn1[4];
#pragma unroll
        for (int j = 0; j < 4; j++) {
            wn0[j] = W0[(kp + j) * 512];
            wn1[j] = W1[(kp + j) * 512];
        }
        // activation broadcasts for this chunk: 8 rows per k as 2x ulonglong2
        ulonglong2 qa[4], qb[4];
#pragma unroll
        for (int j = 0; j < 4; j++) {
            const ulonglong2* xr = (const ulonglong2*)(xhp + (k0 + j) * ROWS);
            qa[j] = xr[0];        // rows 8h+0..3
            qb[j] = xr[1];        // rows 8h+4..7
        }
#pragma unroll
        for (int j = 0; j < 4; j++) {
            acc0[0] = fma2(wc0[j], qa[j].x, acc0[0]);
            acc0[1] = fma2(wc0[j], qa[j].y, acc0[1]);
            acc0[2] = fma2(wc0[j], qb[j].x, acc0[2]);
            acc0[3] = fma2(wc0[j], qb[j].y, acc0[3]);
            acc1[0] = fma2(wc1[j], qa[j].x, acc1[0]);
            acc1[1] = fma2(wc1[j], qa[j].y, acc1[1]);
            acc1[2] = fma2(wc1[j], qb[j].x, acc1[2]);
            acc1[3] = fma2(wc1[j], qb[j].y, acc1[3]);
        }
#pragma unroll
        for (int j = 0; j < 4; j++) { wc0[j] = wn0[j]; wc1[j] = wn1[j]; }
    }

    // write gates: rows 8h+2p, 8h+2p+1; lanes write consecutive g -> coalesced
    const int rb = half * 8;
#pragma unroll
    for (int p = 0; p < 4; p++) {
        float lo, hi;
        unpack2(acc0[p], lo, hi);
        gates[(rb + 2 * p)     * GSTR + g0] = lo;
        gates[(rb + 2 * p + 1) * GSTR + g0] = hi;
        unpack2(acc1[p], lo, hi);
        gates[(rb + 2 * p)     * GSTR + g1] = lo;
        gates[(rb + 2 * p + 1) * GSTR + g1] = hi;
    }
}

// Small MLP layer over the CTA's 16 rows (head only; cost negligible)
__device__ __forceinline__ void mlp_layer(const float* __restrict__ vin, int Din,
                                          const float* __restrict__ W, const float* __restrict__ b,
                                          float* __restrict__ vout, int Dout, bool relu, int tid)
{
    for (int e = tid; e < ROWS * Dout; e += NTHREADS) {
        int r = e / Dout, o = e - r * Dout;
        const float* w = W + o * Din;
        const float* vi = vin + r * Din;
        float s = b[o];
        for (int i = 0; i < Din; i += 4) {
            s += w[i] * vi[i] + w[i + 1] * vi[i + 1] + w[i + 2] * vi[i + 2] + w[i + 3] * vi[i + 3];
        }
        vout[e] = relu ? fmaxf(s, 0.f) : s;
    }
    __syncthreads();
}

// ---------------------------------------------------------------------------
__global__ void __launch_bounds__(NTHREADS, 1)
dfmnet_main(const float* __restrict__ x,
            const float* __restrict__ Wk0, const float* __restrict__ bk0,
            const float* __restrict__ Wk1, const float* __restrict__ bk1,
            const float* __restrict__ Wk2, const float* __restrict__ bk2,
            const float* __restrict__ Wk3, const float* __restrict__ bk3,
            const float* __restrict__ Wk4, const float* __restrict__ bk4,
            const float* __restrict__ Wk5, const float* __restrict__ bk5,
            float* __restrict__ out, int Bn)
{
    extern __shared__ float sm[];
    float* xh    = sm;                      // [KROWS][16]  (k-major, 16 rows)
    float* gates = sm + KROWS * ROWS;       // [16][GSTR]

    const int tid = threadIdx.x;
    const int b0 = blockIdx.x * ROWS;

    for (int e = tid; e < KROWS * ROWS; e += NTHREADS) xh[e] = 0.f;
    float c1r[4], c2r[4];
#pragma unroll
    for (int p = 0; p < 4; p++) { c1r[p] = 0.f; c2r[p] = 0.f; }
    __syncthreads();

    const float* xbase = x + (size_t)b0 * T_SEQ * I_IN;

    for (int t = 0; t < T_SEQ; t++) {
        // load x_t (16 rows x 64) transposed into xh rows [0,64)
#pragma unroll
        for (int q = 0; q < 2; q++) {
            int e = tid + q * NTHREADS;            // 0..1023
            int r = e >> 6, k = e & 63;
            xh[k * ROWS + r] = xbase[(size_t)r * (T_SEQ * I_IN) + t * I_IN + k];
        }
        __syncthreads();

        // layer 1: gates = [x | h1_prev] @ Wt1 + b1
        gemm_gates(g_Wt1, g_b1, xh, gates, 192, tid);
        __syncthreads();

        // layer 1 activation: h1 -> xh rows [64,192)
#pragma unroll
        for (int p = 0; p < 4; p++) {
            int idx = tid + p * NTHREADS;          // 0..2047
            int j = idx >> 4, r = idx & 15;        // 16 r's per j -> coalesced h-write
            const float* gr = gates + r * GSTR + j;
            float iv = sigf(gr[0]);
            float fv = sigf(gr[128]);
            float gv = tanhf_fast(gr[256]);
            float ov = sigf(gr[384]);
            float c = fv * c1r[p] + iv * gv;
            c1r[p] = c;
            xh[(64 + j) * ROWS + r] = ov * tanhf_fast(c);
        }
        __syncthreads();

        // layer 2: gates = [h1 | h2_prev] @ Wt2 + b2  (xh rows [64,320))
        gemm_gates(g_Wt2, g_b2, xh + 64 * ROWS, gates, 256, tid);
        __syncthreads();

        // layer 2 activation: h2 -> xh rows [192,320)
#pragma unroll
        for (int p = 0; p < 4; p++) {
            int idx = tid + p * NTHREADS;
            int j = idx >> 4, r = idx & 15;
            const float* gr = gates + r * GSTR + j;
            float iv = sigf(gr[0]);
            float fv = sigf(gr[128]);
            float gv = tanhf_fast(gr[256]);
            float ov = sigf(gr[384]);
            float c = fv * c2r[p] + iv * gv;
            c2r[p] = c;
            xh[(192 + j) * ROWS + r] = ov * tanhf_fast(c);
        }
        // next iter's x-load writes disjoint smem; its __syncthreads orders
        // these h2 writes before the next layer-2 GEMM.
    }
    __syncthreads();

    // ---- outputs: tuple (y, h2, r) flattened ----
    float* out_y  = out;                              // [Bn][64]
    float* out_h2 = out + (size_t)Bn * 64;            // [Bn][128]
    float* out_r  = out + (size_t)Bn * 192;           // [Bn][192]

    float* va = gates;              // [16][192]
    float* vb = gates + ROWS * 192; // [16][128]
    float* vc = vb + ROWS * 128;    // [16][128]
    for (int e = tid; e < ROWS * 192; e += NTHREADS) {
        int r = e / 192, j = e - r * 192;
        float v = (j < 128) ? xh[(192 + j) * ROWS + r] : xh[(j - 128) * ROWS + r];
        va[e] = v;
        out_r[(size_t)(b0 + r) * 192 + j] = v;
        if (j < 128) out_h2[(size_t)(b0 + r) * 128 + j] = v;
    }
    __syncthreads();

    mlp_layer(va, 192, Wk0, bk0, vb, 128, true, tid);
    mlp_layer(vb, 128, Wk1, bk1, vc, 128, true, tid);
    mlp_layer(vc, 128, Wk2, bk2, vb, 128, true, tid);
    mlp_layer(vb, 128, Wk3, bk3, vc, 128, true, tid);
    mlp_layer(vc, 128, Wk4, bk4, vb, 128, true, tid);

    for (int e = tid; e < ROWS * 64; e += NTHREADS) {
        int r = e >> 6, o = e & 63;
        const float* w = Wk5 + o * 128;
        const float* vi = vb + r * 128;
        float s = bk5[o];
        for (int i = 0; i < 128; i += 4) {
            s += w[i] * vi[i] + w[i + 1] * vi[i + 1] + w[i + 2] * vi[i + 2] + w[i + 3] * vi[i + 3];
        }
        out_y[(size_t)(b0 + r) * 64 + o] = s;
    }
}

// ---------------------------------------------------------------------------
extern "C" void kernel_launch(void* const* d_in, const int* in_sizes, int n_in,
                              void* d_out, int out_size)
{
    const float* x    = (const float*)d_in[0];
    const float* Wih1 = (const float*)d_in[1];
    const float* Whh1 = (const float*)d_in[2];
    const float* bih1 = (const float*)d_in[3];
    const float* bhh1 = (const float*)d_in[4];
    const float* Wih2 = (const float*)d_in[5];
    const float* Whh2 = (const float*)d_in[6];
    const float* bih2 = (const float*)d_in[7];
    const float* bhh2 = (const float*)d_in[8];
    const float* Wk0 = (const float*)d_in[9];   const float* bk0 = (const float*)d_in[10];
    const float* Wk1 = (const float*)d_in[11];  const float* bk1 = (const float*)d_in[12];
    const float* Wk2 = (const float*)d_in[13];  const float* bk2 = (const float*)d_in[14];
    const float* Wk3 = (const float*)d_in[15];  const float* bk3 = (const float*)d_in[16];
    const float* Wk4 = (const float*)d_in[17];  const float* bk4 = (const float*)d_in[18];
    const float* Wk5 = (const float*)d_in[19];  const float* bk5 = (const float*)d_in[20];

    int Bn = in_sizes[0] / (T_SEQ * I_IN);
    int smem_bytes = (KROWS * ROWS + ROWS * GSTR) * (int)sizeof(float);   // 5120+8256 floats = 53504 B

    cudaFuncSetAttribute(dfmnet_main, cudaFuncAttributeMaxDynamicSharedMemorySize, smem_bytes);

    prep_kernel<<<208, 256>>>(Wih1, Whh1, bih1, bhh1, Wih2, Whh2, bih2, bhh2);
    dfmnet_main<<<Bn / ROWS, NTHREADS, smem_bytes>>>(
        x, Wk0, bk0, Wk1, bk1, Wk2, bk2, Wk3, bk3, Wk4, bk4, Wk5, bk5,
        (float*)d_out, Bn);
}